// round 1
// baseline (speedup 1.0000x reference)
#include <cuda_runtime.h>

typedef unsigned int u32;
typedef unsigned long long u64;

static constexpr int Bn  = 4;
static constexpr int Sn  = 4000;
static constexpr int Din = 1024;
static constexpr int Da  = 512;
static constexpr int Ln  = 8921;
static constexpr int M2  = 2 * Ln;       // 17842 rows: [U; V]
static constexpr int M2pad = 17920;      // 140 * 128
static constexpr int Zrows = Bn * Sn;    // 16000
static constexpr int Zpad  = Zrows + 128;

// ---- scratch (device globals; no allocation allowed) ----
__device__ float g_xr [(u64)Bn * Sn * Din];   // x rounded to tf32
__device__ float g_wr [(u64)Da * Din];        // W_w rounded
__device__ float g_uvr[(u64)M2pad * Da];      // [U; V] rounded (padded rows)
__device__ float g_z  [(u64)Zpad * Da];       // z = tanh(xW^T+b), tf32-rounded
__device__ float g_w  [(u64)Bn * Ln * Sn];    // w = V z^T (571 MB)

// ---- helpers ----
__device__ __forceinline__ u32 f2tf(float f) {
    u32 u;
    asm("cvt.rna.tf32.f32 %0, %1;" : "=r"(u) : "f"(f));
    return u;
}

__device__ __forceinline__ void cp16(u32 saddr, const void* g) {
    asm volatile("cp.async.cg.shared.global [%0], [%1], 16;\n" :: "r"(saddr), "l"(g));
}

__device__ __forceinline__ void mma8(float* c, const u32* a, u32 b0, u32 b1) {
    asm volatile(
        "mma.sync.aligned.m16n8k8.row.col.f32.tf32.tf32.f32 "
        "{%0,%1,%2,%3}, {%4,%5,%6,%7}, {%8,%9}, {%0,%1,%2,%3};\n"
        : "+f"(c[0]), "+f"(c[1]), "+f"(c[2]), "+f"(c[3])
        : "r"(a[0]), "r"(a[1]), "r"(a[2]), "r"(a[3]), "r"(b0), "r"(b1));
}

// ---- input rounding to tf32 ----
__global__ void round_k(const float* __restrict__ in, int n4, int sel) {
    int i = blockIdx.x * blockDim.x + threadIdx.x;
    if (i >= n4) return;
    float* out = (sel == 0) ? g_xr
               : (sel == 1) ? g_wr
               : (sel == 2) ? g_uvr
                            : (g_uvr + (u64)Ln * Da);
    float4 v = ((const float4*)in)[i];
    uint4 o;
    o.x = f2tf(v.x); o.y = f2tf(v.y); o.z = f2tf(v.z); o.w = f2tf(v.w);
    ((uint4*)out)[i] = o;
}

// ---- tiled tf32 GEMM: C[m,n] = sum_k A[m,k]*B[n,k] ----
// EPI==0: z-GEMM  (A=g_xr [16000,1024], B=g_wr [512,1024]) -> g_z, tanh+bias, tf32 round
// EPI==1: sw-GEMM (A=g_uvr [17920,512], B=g_z(batch) [4000+,512])
//         rows < Ln -> scores into d_out alpha region; rows >= Ln -> g_w
static constexpr int BM = 128, BN = 128, BK = 32, KS = 36;
static constexpr int TILEF = BM * KS;                 // floats per tile buffer
static constexpr u32 SMEM_BYTES = 4u * TILEF * 4u;    // A0,A1,B0,B1 = 73728 B

template<int EPI>
__global__ void __launch_bounds__(256, 2)
gemm_k(const float* __restrict__ bias, float* __restrict__ dout) {
    constexpr int K   = (EPI == 0) ? Din : Da;
    constexpr int KIT = K / BK;

    extern __shared__ float smem[];
    float* As = smem;
    float* Bs = smem + 2 * TILEF;

    const int tid   = threadIdx.x;
    const int nbase = blockIdx.x * BN;
    const int mbase = blockIdx.y * BM;
    const int bz    = blockIdx.z;

    const float* Ag = (EPI == 0) ? g_xr : g_uvr;
    const float* Bg = (EPI == 0) ? g_wr : (g_z + (u64)bz * Sn * Da);

    const int lr = tid >> 3;         // 0..31
    const int lc = (tid & 7) * 4;    // 0..28
    const float* aG = Ag + (u64)(mbase + lr) * K + lc;
    const float* bG = Bg + (u64)(nbase + lr) * K + lc;

    u32 sA = (u32)__cvta_generic_to_shared(As + lr * KS + lc);
    u32 sB = (u32)__cvta_generic_to_shared(Bs + lr * KS + lc);
    const u32 bufB = (u32)TILEF * 4u;

    auto issue = [&](int kt, int buf) {
        const float* a = aG + kt * BK;
        const float* b = bG + kt * BK;
#pragma unroll
        for (int i = 0; i < 4; i++) cp16(sA + buf * bufB + i * (32 * KS * 4), a + (u64)i * 32 * K);
#pragma unroll
        for (int i = 0; i < 4; i++) cp16(sB + buf * bufB + i * (32 * KS * 4), b + (u64)i * 32 * K);
    };

    issue(0, 0); asm volatile("cp.async.commit_group;\n");
    issue(1, 1); asm volatile("cp.async.commit_group;\n");

    const int warp = tid >> 5, lane = tid & 31;
    const int g = lane >> 2, tg = lane & 3;
    const int wm = warp & 3, wn = warp >> 2;   // 4 x 2 warp grid (M x N)

    float c[2][8][4];
#pragma unroll
    for (int mf = 0; mf < 2; mf++)
#pragma unroll
        for (int nf = 0; nf < 8; nf++)
#pragma unroll
            for (int i = 0; i < 4; i++) c[mf][nf][i] = 0.f;

    for (int kt = 0; kt < KIT; kt++) {
        if (kt == KIT - 1) asm volatile("cp.async.wait_group 0;\n");
        else               asm volatile("cp.async.wait_group 1;\n");
        __syncthreads();

        const float* as = As + (kt & 1) * TILEF + (wm * 32) * KS;
        const float* bs = Bs + (kt & 1) * TILEF + (wn * 64) * KS;
#pragma unroll
        for (int ks = 0; ks < 4; ks++) {
            const int k0 = ks * 8;
            u32 a[2][4];
#pragma unroll
            for (int mf = 0; mf < 2; mf++) {
                const float* ar = as + (mf * 16) * KS;
                a[mf][0] = __float_as_uint(ar[(g    ) * KS + k0 + tg    ]);
                a[mf][1] = __float_as_uint(ar[(g + 8) * KS + k0 + tg    ]);
                a[mf][2] = __float_as_uint(ar[(g    ) * KS + k0 + tg + 4]);
                a[mf][3] = __float_as_uint(ar[(g + 8) * KS + k0 + tg + 4]);
            }
#pragma unroll
            for (int nf = 0; nf < 8; nf++) {
                u32 b0 = __float_as_uint(bs[(nf * 8 + g) * KS + k0 + tg    ]);
                u32 b1 = __float_as_uint(bs[(nf * 8 + g) * KS + k0 + tg + 4]);
                mma8(c[0][nf], a[0], b0, b1);
                mma8(c[1][nf], a[1], b0, b1);
            }
        }
        __syncthreads();
        if (kt + 2 < KIT) { issue(kt + 2, kt & 1); asm volatile("cp.async.commit_group;\n"); }
    }

    // epilogue
#pragma unroll
    for (int mf = 0; mf < 2; mf++) {
#pragma unroll
        for (int nf = 0; nf < 8; nf++) {
            const int r  = mbase + wm * 32 + mf * 16 + g;
            const int cl = nbase + wn * 64 + nf * 8 + 2 * tg;
            float* cc = c[mf][nf];
            if (EPI == 0) {
                const float b0 = bias[cl], b1 = bias[cl + 1];
                float2 o;
                o.x = __uint_as_float(f2tf(tanhf(cc[0] + b0)));
                o.y = __uint_as_float(f2tf(tanhf(cc[1] + b1)));
                *(float2*)(g_z + (u64)r * Da + cl) = o;
                o.x = __uint_as_float(f2tf(tanhf(cc[2] + b0)));
                o.y = __uint_as_float(f2tf(tanhf(cc[3] + b1)));
                *(float2*)(g_z + (u64)(r + 8) * Da + cl) = o;
            } else {
                if (cl < Sn) {
                    if (r < M2) {
                        float* dst = (r < Ln)
                            ? (dout + ((u64)bz * Ln + r) * Sn + cl)
                            : (g_w  + ((u64)bz * Ln + (r - Ln)) * Sn + cl);
                        *(float2*)dst = make_float2(cc[0], cc[1]);
                    }
                    const int r2 = r + 8;
                    if (r2 < M2) {
                        float* dst = (r2 < Ln)
                            ? (dout + ((u64)bz * Ln + r2) * Sn + cl)
                            : (g_w  + ((u64)bz * Ln + (r2 - Ln)) * Sn + cl);
                        *(float2*)dst = make_float2(cc[2], cc[3]);
                    }
                }
            }
        }
    }
}

// ---- block reduction (256 threads, 8 warps) ----
__device__ __forceinline__ float bred(float v, float* red, bool sum) {
#pragma unroll
    for (int o = 16; o; o >>= 1) {
        float t = __shfl_xor_sync(0xffffffffu, v, o);
        v = sum ? (v + t) : fmaxf(v, t);
    }
    __syncthreads();  // protect red[] from a previous use
    if ((threadIdx.x & 31) == 0) red[threadIdx.x >> 5] = v;
    __syncthreads();
    float out = red[0];
#pragma unroll
    for (int i = 1; i < 8; i++) out = sum ? (out + red[i]) : fmaxf(out, red[i]);
    return out;
}

// ---- finalize: softmax over each (b,l) row (in place in d_out) + y = sum alpha*w ----
__global__ void __launch_bounds__(256)
finalize_k(float* __restrict__ dout, const float* __restrict__ Vb) {
    const int bid = blockIdx.x;
    const int b = bid / Ln;
    const int l = bid - b * Ln;
    float*       arow = dout + (u64)Bn * Ln + ((u64)b * Ln + l) * Sn;  // scores in, alpha out
    const float* wrow = g_w  + ((u64)b * Ln + l) * Sn;
    const int tid = threadIdx.x;
    __shared__ float red[8];

    const int base = tid * 4;
    float4 r[4];
    float mx = -3.402823466e38f;
#pragma unroll
    for (int j = 0; j < 4; j++) {
        const int i = base + j * 1024;
        if (i < Sn) {
            r[j] = *(const float4*)(arow + i);
            mx = fmaxf(mx, fmaxf(fmaxf(r[j].x, r[j].y), fmaxf(r[j].z, r[j].w)));
        }
    }
    mx = bred(mx, red, false);

    float s = 0.f;
#pragma unroll
    for (int j = 0; j < 4; j++) {
        const int i = base + j * 1024;
        if (i < Sn) {
            r[j].x = __expf(r[j].x - mx);
            r[j].y = __expf(r[j].y - mx);
            r[j].z = __expf(r[j].z - mx);
            r[j].w = __expf(r[j].w - mx);
            s += r[j].x + r[j].y + r[j].z + r[j].w;
        }
    }
    s = bred(s, red, true);
    const float inv = 1.f / s;

    float y = 0.f;
#pragma unroll
    for (int j = 0; j < 4; j++) {
        const int i = base + j * 1024;
        if (i < Sn) {
            float4 w4 = *(const float4*)(wrow + i);
            float4 a4;
            a4.x = r[j].x * inv; a4.y = r[j].y * inv;
            a4.z = r[j].z * inv; a4.w = r[j].w * inv;
            *(float4*)(arow + i) = a4;
            y += a4.x * w4.x + a4.y * w4.y + a4.z * w4.z + a4.w * w4.w;
        }
    }
    y = bred(y, red, true);
    if (tid == 0) dout[(u64)b * Ln + l] = y + Vb[l];
}

// ---- launch ----
extern "C" void kernel_launch(void* const* d_in, const int* in_sizes, int n_in,
                              void* d_out, int out_size) {
    const float* x  = (const float*)d_in[0];
    const float* Ww = (const float*)d_in[1];
    const float* Wb = (const float*)d_in[2];
    const float* Uw = (const float*)d_in[3];
    const float* Vw = (const float*)d_in[4];
    const float* Vb = (const float*)d_in[5];
    float* out = (float*)d_out;

    cudaFuncSetAttribute(gemm_k<0>, cudaFuncAttributeMaxDynamicSharedMemorySize, (int)SMEM_BYTES);
    cudaFuncSetAttribute(gemm_k<1>, cudaFuncAttributeMaxDynamicSharedMemorySize, (int)SMEM_BYTES);

    // round inputs to tf32 (float4 element counts)
    round_k<<<(4096000 + 255) / 256, 256>>>(x,  4096000, 0);
    round_k<<<( 131072 + 255) / 256, 256>>>(Ww,  131072, 1);
    round_k<<<(1141888 + 255) / 256, 256>>>(Uw, 1141888, 2);
    round_k<<<(1141888 + 255) / 256, 256>>>(Vw, 1141888, 3);

    // z = tanh(x W^T + b)
    gemm_k<0><<<dim3(4, 125, 1), 256, SMEM_BYTES>>>(Wb, nullptr);
    // [scores; w] = [U; V] z^T  (scores -> d_out alpha region, w -> g_w)
    gemm_k<1><<<dim3(32, 140, 4), 256, SMEM_BYTES>>>(nullptr, out + (u64)Bn * Ln);
    // softmax rows in place + y
    finalize_k<<<Bn * Ln, 256>>>(out, Vb);
}